// round 14
// baseline (speedup 1.0000x reference)
#include <cuda_runtime.h>
#include <math.h>

#define NB 16
#define NN 512
#define NH 8
#define ND 32
#define NE 16
#define NHID 256
#define GHEADS 4
#define ATT_SCALE 0.17677669529663687f  // 32^-0.5

#define PSTRIDE 516   // P row stride in floats: multiple of 4 -> float4-aligned rows

// ---- packed fp32x2 helpers (B300 FFMA2: halves issue slots for fp32 FMA pairs) ----
#define PACKF2(out, x) \
    asm("mov.b64 %0, {%1, %1};" : "=l"(out) : "r"(__float_as_uint(x)))
#define FMA2(d, a, b) \
    asm("fma.rn.f32x2 %0, %1, %2, %0;" : "+l"(d) : "l"(a), "l"(b))
#define UNPACKF2(lo, hi, v) do { unsigned int _u, _v;                         \
    asm("mov.b64 {%0, %1}, %2;" : "=r"(_u), "=r"(_v) : "l"(v));               \
    lo = __uint_as_float(_u); hi = __uint_as_float(_v); } while (0)

// ---------------- device scratch (no allocations allowed) ----------------
__device__ float g_qh [NB*NH*NN*ND];   // [b][h][n][d]
__device__ float g_kh [NB*NH*NN*ND];
__device__ float g_vh [NB*NH*NN*ND];
__device__ float g_qhT[NB*NH*ND*NN];   // [b][h][d][n]
__device__ float g_khT[NB*NH*ND*NN];
__device__ float g_qke[NB*NH*NN*NE];   // qe + ke (both gathered at row i!)
__device__ float g_ao [NB*NN*NHID];    // attention output, [b][n][h*D+d]

struct QKVPtrs {
    const float* X[3];
    const float* W[3];
    const float* Bv[3];
};

// ---------------- shared GEMM mainloop: 128x64 tile, 8x4 micro-tile ----------------
__device__ __forceinline__ void gemm_core(const float* __restrict__ Xp,
                                          const float* __restrict__ W,
                                          float (*sA)[130], float (*sB)[70],
                                          unsigned long long accP[4][4],
                                          int m0, int o0, int tid, int ty, int tx)
{
    int lmA = tid >> 1, lkA = (tid & 1) * 8;
    int lmB = tid >> 2, lkB = (tid & 3) * 4;
    for (int kc = 0; kc < 256; kc += 16) {
        float4 xa0 = *(const float4*)&Xp[(m0 + lmA) * 256 + kc + lkA];
        float4 xa1 = *(const float4*)&Xp[(m0 + lmA) * 256 + kc + lkA + 4];
        float4 xb  = *(const float4*)&W [(o0 + lmB) * 256 + kc + lkB];
        __syncthreads();
        sA[lkA+0][lmA] = xa0.x; sA[lkA+1][lmA] = xa0.y; sA[lkA+2][lmA] = xa0.z; sA[lkA+3][lmA] = xa0.w;
        sA[lkA+4][lmA] = xa1.x; sA[lkA+5][lmA] = xa1.y; sA[lkA+6][lmA] = xa1.z; sA[lkA+7][lmA] = xa1.w;
        sB[lkB+0][lmB] = xb.x;  sB[lkB+1][lmB] = xb.y;  sB[lkB+2][lmB] = xb.z;  sB[lkB+3][lmB] = xb.w;
        __syncthreads();
        #pragma unroll
        for (int kk = 0; kk < 16; kk++) {
            unsigned long long a0 = *(unsigned long long*)&sA[kk][ty * 8];
            unsigned long long a1 = *(unsigned long long*)&sA[kk][ty * 8 + 2];
            unsigned long long a2 = *(unsigned long long*)&sA[kk][ty * 8 + 4];
            unsigned long long a3 = *(unsigned long long*)&sA[kk][ty * 8 + 6];
            float2 b01 = *(float2*)&sB[kk][tx * 4];
            float2 b23 = *(float2*)&sB[kk][tx * 4 + 2];
            unsigned long long bs0, bs1, bs2, bs3;
            PACKF2(bs0, b01.x); PACKF2(bs1, b01.y); PACKF2(bs2, b23.x); PACKF2(bs3, b23.y);
            FMA2(accP[0][0], a0, bs0); FMA2(accP[0][1], a0, bs1);
            FMA2(accP[0][2], a0, bs2); FMA2(accP[0][3], a0, bs3);
            FMA2(accP[1][0], a1, bs0); FMA2(accP[1][1], a1, bs1);
            FMA2(accP[1][2], a1, bs2); FMA2(accP[1][3], a1, bs3);
            FMA2(accP[2][0], a2, bs0); FMA2(accP[2][1], a2, bs1);
            FMA2(accP[2][2], a2, bs2); FMA2(accP[2][3], a2, bs3);
            FMA2(accP[3][0], a3, bs0); FMA2(accP[3][1], a3, bs1);
            FMA2(accP[3][2], a3, bs2); FMA2(accP[3][3], a3, bs3);
        }
    }
}

__device__ __forceinline__ void unpack_acc(unsigned long long accP[4][4], float acc[8][4])
{
    #pragma unroll
    for (int rp = 0; rp < 4; rp++)
        #pragma unroll
        for (int c = 0; c < 4; c++)
            UNPACKF2(acc[2*rp][c], acc[2*rp+1][c], accP[rp][c]);
}

// ---------------- fused Q/K/V projection GEMM (blockIdx.z selects q/k/v) ----------------
__global__ __launch_bounds__(256) void qkv_gemm(QKVPtrs P)
{
    __shared__ float sA[16][130];
    __shared__ float sB[16][70];

    int which = blockIdx.z;
    int m0 = blockIdx.x * 128;
    int o0 = blockIdx.y * 64;
    int tid = threadIdx.x;
    int ty = tid >> 4;          // 0..15 -> 8 m-rows
    int tx = tid & 15;          // 0..15 -> 4 o-cols

    unsigned long long accP[4][4];
    #pragma unroll
    for (int r = 0; r < 4; r++)
        #pragma unroll
        for (int c = 0; c < 4; c++) accP[r][c] = 0ull;

    gemm_core(P.X[which], P.W[which], sA, sB, accP, m0, o0, tid, ty, tx);

    float acc[8][4];
    unpack_acc(accP, acc);

    int oo = o0 + tx * 4;
    float4 bb = *(const float4*)&P.Bv[which][oo];
    float* dst  = (which == 0) ? g_qh : ((which == 1) ? g_kh : g_vh);
    float* dstT = (which == 0) ? g_qhT : g_khT;   // used only when which < 2
    int h = oo >> 5, d = oo & (ND - 1);
    #pragma unroll
    for (int r = 0; r < 8; r++) {
        int m = m0 + ty * 8 + r;
        float4 y;
        y.x = acc[r][0] + bb.x;
        y.y = acc[r][1] + bb.y;
        y.z = acc[r][2] + bb.z;
        y.w = acc[r][3] + bb.w;
        int b = m >> 9, n = m & (NN - 1);
        *(float4*)&dst[(((b * NH + h) * NN) + n) * ND + d] = y;
        if (which < 2) {
            int base = ((b * NH + h) * ND + d) * NN + n;
            dstT[base         ] = y.x;
            dstT[base +     NN] = y.y;
            dstT[base + 2 * NN] = y.z;
            dstT[base + 3 * NN] = y.w;
        }
    }
}

// ---------------- output projection GEMM: out = g_ao @ Wo^T + bo ----------------
__global__ __launch_bounds__(256) void out_gemm(const float* __restrict__ W,
                                                const float* __restrict__ bias,
                                                float* __restrict__ out)
{
    __shared__ float sA[16][130];
    __shared__ float sB[16][70];

    int m0 = blockIdx.x * 128;
    int o0 = blockIdx.y * 64;
    int tid = threadIdx.x;
    int ty = tid >> 4;
    int tx = tid & 15;

    unsigned long long accP[4][4];
    #pragma unroll
    for (int r = 0; r < 4; r++)
        #pragma unroll
        for (int c = 0; c < 4; c++) accP[r][c] = 0ull;

    gemm_core(g_ao, W, sA, sB, accP, m0, o0, tid, ty, tx);

    float acc[8][4];
    unpack_acc(accP, acc);

    int oo = o0 + tx * 4;
    float4 bb = *(const float4*)&bias[oo];
    #pragma unroll
    for (int r = 0; r < 8; r++) {
        int m = m0 + ty * 8 + r;
        float4 y;
        y.x = acc[r][0] + bb.x;
        y.y = acc[r][1] + bb.y;
        y.z = acc[r][2] + bb.z;
        y.w = acc[r][3] + bb.w;
        *(float4*)&out[m * NHID + oo] = y;
    }
}

// ---------------- combined edge-type score table: g_qke[b][h][n][e] ----------------
__global__ __launch_bounds__(256) void edge_kernel(const float* __restrict__ qemb,
                                                   const float* __restrict__ kemb)
{
    int bh = blockIdx.x;
    int h = bh & (NH - 1);
    __shared__ float sq[NE * ND], sk[NE * ND];
    int tid = threadIdx.x;
    for (int t = tid; t < NE * ND; t += 256) {
        int e = t >> 5, d = t & 31;
        sq[t] = qemb[e * (NH * ND) + h * ND + d];
        sk[t] = kemb[e * (NH * ND) + h * ND + d];
    }
    __syncthreads();

    int n = blockIdx.y * 256 + tid;
    const float4* q4 = (const float4*)&g_qh[((size_t)bh * NN + n) * ND];
    const float4* k4 = (const float4*)&g_kh[((size_t)bh * NN + n) * ND];

    float acc[NE];
    #pragma unroll
    for (int e = 0; e < NE; e++) acc[e] = 0.f;

    #pragma unroll
    for (int g = 0; g < 8; g++) {
        float4 qv = q4[g];
        float4 kv = k4[g];
        #pragma unroll
        for (int e = 0; e < NE; e++) {
            const float4 s1 = *(const float4*)&sq[e * ND + g * 4];
            const float4 s2 = *(const float4*)&sk[e * ND + g * 4];
            float a = acc[e];
            a = fmaf(qv.x, s1.x, a);
            a = fmaf(qv.y, s1.y, a);
            a = fmaf(qv.z, s1.z, a);
            a = fmaf(qv.w, s1.w, a);
            a = fmaf(kv.x, s2.x, a);
            a = fmaf(kv.y, s2.y, a);
            a = fmaf(kv.z, s2.z, a);
            a = fmaf(kv.w, s2.w, a);
            acc[e] = a;
        }
    }

    float4* out = (float4*)&g_qke[((size_t)bh * NN + n) * NE];
    out[0] = make_float4(acc[0],  acc[1],  acc[2],  acc[3]);
    out[1] = make_float4(acc[4],  acc[5],  acc[6],  acc[7]);
    out[2] = make_float4(acc[8],  acc[9],  acc[10], acc[11]);
    out[3] = make_float4(acc[12], acc[13], acc[14], acc[15]);
}

// ---------------- fused attention: one CTA = (b, h, 32-row i-tile) ----------------
// Scores in registers; shuffle softmax; normalized P overwrites dead K^T buffer.
// PV: V staged through smem in 64-row (8KB) chunks, reusing the DEAD sQT/sQE/sMb
// region (exactly 2048 floats) -> per-CTA V gmem traffic drops 8x (512KB -> 64KB),
// killing the ~1GB/launch L2 bottleneck while keeping 2 CTAs/SM.
// smem: buf0 (K^T -> P) 66KB | sQT/sQE/sMb (-> V chunk) 8KB   = 74,240 B
__global__ __launch_bounds__(256, 2) void attn_kernel(const int* __restrict__ edge_attr,
                                                      const int* __restrict__ mask,
                                                      const int* __restrict__ fmask)
{
    extern __shared__ float sm[];
    float* buf0 = sm;                 // 16512 floats: K^T [d][512], then P [32] stride 516
    float* sQT  = sm + 16512;         // [d][32]   (dead after QK^T -> V chunk buffer)
    float* sQE  = sQT + 1024;         // [32][16]  (dead after score epilogue)
    float* sMb  = sQE + 512;          // key mask  (dead after score epilogue)

    int it = blockIdx.x, h = blockIdx.y, b = blockIdx.z;
    int bh = b * NH + h;
    int gi0 = it * 32;
    int tid = threadIdx.x;

    {   // K^T tile: contiguous 64KB copy
        const float4* srcK = (const float4*)(g_khT + (size_t)bh * ND * NN);
        float4* dstK = (float4*)buf0;
        for (int t = tid; t < 4096; t += 256) dstK[t] = srcK[t];
    }
    {   // Q^T 32x32 sub-tile
        const float* qT = g_qhT + (size_t)bh * ND * NN;
        for (int t = tid; t < 1024; t += 256)
            sQT[t] = qT[(t >> 5) * NN + gi0 + (t & 31)];
    }
    {   // combined edge table rows for this i-tile
        const float* src = g_qke + ((size_t)bh * NN + gi0) * NE;
        for (int t = tid; t < 512; t += 256) sQE[t] = src[t];
    }
    for (int t = tid; t < NN; t += 256)
        sMb[t] = mask[b * NN + t] ? 0.f : -INFINITY;
    __syncthreads();

    int tr = tid >> 5, tc = tid & 31;   // tr: i-group (warp id), tc: lane
    int i0 = tr * 4;
    const ulonglong2* KT2 = (const ulonglong2*)buf0;   // [d][128] col-pairs
    const float4*     QT4 = (const float4*)sQT;        // [d][8]
    bool focal = (h >= GHEADS);

    // ---- S = scale*(Q K^T + bias) + mask, kept in registers ----
    float S[4][16];   // [row a][pass*4 + c]
    #pragma unroll
    for (int pass = 0; pass < 4; pass++) {
        int jg = pass * 32 + tc;
        unsigned long long accP[4][2];
        #pragma unroll
        for (int a = 0; a < 4; a++) { accP[a][0] = 0ull; accP[a][1] = 0ull; }
        #pragma unroll 8
        for (int d = 0; d < 32; d++) {
            ulonglong2 k2 = KT2[d * 128 + jg];         // (c0,c1),(c2,c3)
            float4 q4 = QT4[d * 8 + tr];
            unsigned long long qs0, qs1, qs2, qs3;
            PACKF2(qs0, q4.x); PACKF2(qs1, q4.y); PACKF2(qs2, q4.z); PACKF2(qs3, q4.w);
            FMA2(accP[0][0], qs0, k2.x); FMA2(accP[0][1], qs0, k2.y);
            FMA2(accP[1][0], qs1, k2.x); FMA2(accP[1][1], qs1, k2.y);
            FMA2(accP[2][0], qs2, k2.x); FMA2(accP[2][1], qs2, k2.y);
            FMA2(accP[3][0], qs3, k2.x); FMA2(accP[3][1], qs3, k2.y);
        }
        int j0 = jg * 4;
        #pragma unroll
        for (int a = 0; a < 4; a++) {
            float ac0, ac1, ac2, ac3;
            UNPACKF2(ac0, ac1, accP[a][0]);
            UNPACKF2(ac2, ac3, accP[a][1]);
            int gi = gi0 + i0 + a;
            int4 e4 = *(const int4*)&edge_attr[((size_t)b * NN + gi) * NN + j0];
            float mb0, mb1, mb2, mb3;
            if (focal) {
                int4 f4 = *(const int4*)&fmask[((size_t)b * NN + gi) * NN + j0];
                mb0 = f4.x ? 0.f : -INFINITY;
                mb1 = f4.y ? 0.f : -INFINITY;
                mb2 = f4.z ? 0.f : -INFINITY;
                mb3 = f4.w ? 0.f : -INFINITY;
            } else {
                mb0 = sMb[j0]; mb1 = sMb[j0+1]; mb2 = sMb[j0+2]; mb3 = sMb[j0+3];
            }
            const float* qe = &sQE[(i0 + a) * NE];
            S[a][pass*4+0] = (ac0 + qe[e4.x]) * ATT_SCALE + mb0;
            S[a][pass*4+1] = (ac1 + qe[e4.y]) * ATT_SCALE + mb1;
            S[a][pass*4+2] = (ac2 + qe[e4.z]) * ATT_SCALE + mb2;
            S[a][pass*4+3] = (ac3 + qe[e4.w]) * ATT_SCALE + mb3;
        }
    }

    // ---- softmax fully in registers: row a is spread over this warp's 32 lanes ----
    #pragma unroll
    for (int a = 0; a < 4; a++) {
        float m = S[a][0];
        #pragma unroll
        for (int c = 1; c < 16; c++) m = fmaxf(m, S[a][c]);
        m = fmaxf(m, __shfl_xor_sync(0xffffffffu, m, 16));
        m = fmaxf(m, __shfl_xor_sync(0xffffffffu, m, 8));
        m = fmaxf(m, __shfl_xor_sync(0xffffffffu, m, 4));
        m = fmaxf(m, __shfl_xor_sync(0xffffffffu, m, 2));
        m = fmaxf(m, __shfl_xor_sync(0xffffffffu, m, 1));
        float l = 0.f;
        #pragma unroll
        for (int c = 0; c < 16; c++) {
            float p = __expf(S[a][c] - m);
            S[a][c] = p;
            l += p;
        }
        l += __shfl_xor_sync(0xffffffffu, l, 16);
        l += __shfl_xor_sync(0xffffffffu, l, 8);
        l += __shfl_xor_sync(0xffffffffu, l, 4);
        l += __shfl_xor_sync(0xffffffffu, l, 2);
        l += __shfl_xor_sync(0xffffffffu, l, 1);
        float inv = 1.f / l;
        #pragma unroll
        for (int c = 0; c < 16; c++) S[a][c] *= inv;
    }

    __syncthreads();   // all warps done reading K^T (and sQE/sMb) -> safe to overwrite

    // ---- write normalized P over the dead K^T buffer, [i][j] stride PSTRIDE ----
    #pragma unroll
    for (int pass = 0; pass < 4; pass++) {
        int j0 = (pass * 32 + tc) * 4;
        #pragma unroll
        for (int a = 0; a < 4; a++)
            *(float4*)&buf0[(i0 + a) * PSTRIDE + j0] =
                make_float4(S[a][pass*4+0], S[a][pass*4+1], S[a][pass*4+2], S[a][pass*4+3]);
    }

    // ---- O = P V: V staged in 64-row smem chunks over the dead sQT region ----
    {
        int dg = tc & 7, js = tc >> 3;
        float* sVC = sQT;                                   // 2048 floats = 64 rows x 32
        const float4* srcV = (const float4*)(g_vh + (size_t)bh * NN * ND);
        unsigned long long oP[4][2];
        #pragma unroll
        for (int a = 0; a < 4; a++) { oP[a][0] = 0ull; oP[a][1] = 0ull; }

        #pragma unroll 1
        for (int c = 0; c < 8; c++) {
            __syncthreads();    // prev chunk consumed (and, at c=0, P writes/score reads done)
            ((float4*)sVC)[tid]       = srcV[c * 512 + tid];
            ((float4*)sVC)[tid + 256] = srcV[c * 512 + tid + 256];
            __syncthreads();
            const ulonglong2* V2 = (const ulonglong2*)sVC;  // [jj][8] d-pairs
            int jbase = c * 64;
            #pragma unroll 4
            for (int jj = js; jj < 64; jj += 4) {
                ulonglong2 vv = V2[jj * 8 + dg];            // (d0,d1),(d2,d3)
                int j = jbase + jj;
                float p0 = buf0[(i0+0) * PSTRIDE + j];
                float p1 = buf0[(i0+1) * PSTRIDE + j];
                float p2 = buf0[(i0+2) * PSTRIDE + j];
                float p3 = buf0[(i0+3) * PSTRIDE + j];
                unsigned long long ps0, ps1, ps2, ps3;
                PACKF2(ps0, p0); PACKF2(ps1, p1); PACKF2(ps2, p2); PACKF2(ps3, p3);
                FMA2(oP[0][0], ps0, vv.x); FMA2(oP[0][1], ps0, vv.y);
                FMA2(oP[1][0], ps1, vv.x); FMA2(oP[1][1], ps1, vv.y);
                FMA2(oP[2][0], ps2, vv.x); FMA2(oP[2][1], ps2, vv.y);
                FMA2(oP[3][0], ps3, vv.x); FMA2(oP[3][1], ps3, vv.y);
            }
        }

        float4 o0, o1, o2, o3;
        UNPACKF2(o0.x, o0.y, oP[0][0]); UNPACKF2(o0.z, o0.w, oP[0][1]);
        UNPACKF2(o1.x, o1.y, oP[1][0]); UNPACKF2(o1.z, o1.w, oP[1][1]);
        UNPACKF2(o2.x, o2.y, oP[2][0]); UNPACKF2(o2.z, o2.w, oP[2][1]);
        UNPACKF2(o3.x, o3.y, oP[3][0]); UNPACKF2(o3.z, o3.w, oP[3][1]);
        #define WRED(v) \
            v.x += __shfl_xor_sync(0xffffffffu, v.x, 8);  v.x += __shfl_xor_sync(0xffffffffu, v.x, 16); \
            v.y += __shfl_xor_sync(0xffffffffu, v.y, 8);  v.y += __shfl_xor_sync(0xffffffffu, v.y, 16); \
            v.z += __shfl_xor_sync(0xffffffffu, v.z, 8);  v.z += __shfl_xor_sync(0xffffffffu, v.z, 16); \
            v.w += __shfl_xor_sync(0xffffffffu, v.w, 8);  v.w += __shfl_xor_sync(0xffffffffu, v.w, 16);
        WRED(o0) WRED(o1) WRED(o2) WRED(o3)
        #undef WRED
        if (js == 0) {
            int col = h * ND + dg * 4;
            size_t rb = ((size_t)b * NN + gi0 + i0) * NHID;
            *(float4*)&g_ao[rb            + col] = o0;
            *(float4*)&g_ao[rb +     NHID + col] = o1;
            *(float4*)&g_ao[rb + 2 * NHID + col] = o2;
            *(float4*)&g_ao[rb + 3 * NHID + col] = o3;
        }
    }
}

// ---------------- launch ----------------
extern "C" void kernel_launch(void* const* d_in, const int* in_sizes, int n_in,
                              void* d_out, int out_size)
{
    const float* q    = (const float*)d_in[0];
    const float* k    = (const float*)d_in[1];
    const float* v    = (const float*)d_in[2];
    const float* qemb = (const float*)d_in[3];
    const float* kemb = (const float*)d_in[4];
    const int*   eatt = (const int*)d_in[5];
    const int*   mask  = (const int*)d_in[6];
    const int*   fmask = (const int*)d_in[7];
    const float* Wq = (const float*)d_in[8];
    const float* bq = (const float*)d_in[9];
    const float* Wk = (const float*)d_in[10];
    const float* bk = (const float*)d_in[11];
    const float* Wv = (const float*)d_in[12];
    const float* bv = (const float*)d_in[13];
    const float* Wo = (const float*)d_in[14];
    const float* bo = (const float*)d_in[15];
    float* out = (float*)d_out;

    QKVPtrs P;
    P.X[0] = q;  P.X[1] = k;  P.X[2] = v;
    P.W[0] = Wq; P.W[1] = Wk; P.W[2] = Wv;
    P.Bv[0] = bq; P.Bv[1] = bk; P.Bv[2] = bv;

    qkv_gemm<<<dim3(64, 4, 3), 256>>>(P);

    edge_kernel<<<dim3(NB * NH, 2), 256>>>(qemb, kemb);

    int smem_bytes = (16512 + 1024 + 512 + 512) * 4;  // 74,240 B -> 2 CTAs/SM
    cudaFuncSetAttribute(attn_kernel, cudaFuncAttributeMaxDynamicSharedMemorySize, smem_bytes);
    attn_kernel<<<dim3(NN / 32, NH, NB), 256, smem_bytes>>>(eatt, mask, fmask);

    out_gemm<<<dim3(64, 4), 256>>>(Wo, bo, out);
}

// round 16
// speedup vs baseline: 1.0895x; 1.0895x over previous
#include <cuda_runtime.h>
#include <math.h>

#define NB 16
#define NN 512
#define NH 8
#define ND 32
#define NE 16
#define NHID 256
#define GHEADS 4
#define ATT_SCALE 0.17677669529663687f  // 32^-0.5

#define PSTRIDE 516   // P row stride in floats: multiple of 4 -> float4-aligned rows
#define SA 20         // smem k-stride for mma tiles: (20r+c)%32 all-distinct -> conflict-free

// ---- packed fp32x2 helpers (kept for attention kernel) ----
#define PACKF2(out, x) \
    asm("mov.b64 %0, {%1, %1};" : "=l"(out) : "r"(__float_as_uint(x)))
#define FMA2(d, a, b) \
    asm("fma.rn.f32x2 %0, %1, %2, %0;" : "+l"(d) : "l"(a), "l"(b))
#define UNPACKF2(lo, hi, v) do { unsigned int _u, _v;                         \
    asm("mov.b64 {%0, %1}, %2;" : "=r"(_u), "=r"(_v) : "l"(v));               \
    lo = __uint_as_float(_u); hi = __uint_as_float(_v); } while (0)

// ---- tf32 mma helpers ----
__device__ __forceinline__ void f2tf2(float x, unsigned int& hi, unsigned int& lo) {
    unsigned int h;
    asm("cvt.rna.tf32.f32 %0, %1;" : "=r"(h) : "f"(x));
    float l = x - __uint_as_float(h);   // exact: hi is x with truncated mantissa
    unsigned int lw;
    asm("cvt.rna.tf32.f32 %0, %1;" : "=r"(lw) : "f"(l));
    hi = h; lo = lw;
}

#define MMA_TF32(d, a, b) \
    asm("mma.sync.aligned.m16n8k8.row.col.f32.tf32.tf32.f32 " \
        "{%0,%1,%2,%3}, {%4,%5,%6,%7}, {%8,%9}, {%0,%1,%2,%3};" \
        : "+f"(d[0]), "+f"(d[1]), "+f"(d[2]), "+f"(d[3]) \
        : "r"(a[0]), "r"(a[1]), "r"(a[2]), "r"(a[3]), "r"(b[0]), "r"(b[1]))

// ---------------- device scratch (no allocations allowed) ----------------
__device__ float g_qh [NB*NH*NN*ND];   // [b][h][n][d]
__device__ float g_kh [NB*NH*NN*ND];
__device__ float g_vh [NB*NH*NN*ND];
__device__ float g_qhT[NB*NH*ND*NN];   // [b][h][d][n]
__device__ float g_khT[NB*NH*ND*NN];
__device__ float g_qke[NB*NH*NN*NE];   // qe + ke (both gathered at row i!)
__device__ float g_ao [NB*NN*NHID];    // attention output, [b][n][h*D+d]

struct QKVPtrs {
    const float* X[3];
    const float* W[3];
    const float* Bv[3];
};

// ---------------- 3xTF32 tensor-core GEMM mainloop: 128x64 tile ----------------
// 256 threads = 8 warps in 4(m) x 2(n) grid of 32x32 warp tiles.
// k-chunk 16 (two k=8 mma steps). smem planes: hi/lo of A [m][k] and B=W [o][k]
// (W's natural [o][k] layout IS the col-major B that mma row.col expects).
// Split: D += Ahi*Bhi + Ahi*Blo + Alo*Bhi  -> ~fp32 accuracy on tensor pipe.
__device__ __forceinline__ void gemm_core_mma(const float* __restrict__ Xp,
                                              const float* __restrict__ W,
                                              unsigned int (*sAb)[128][SA],
                                              unsigned int (*sBb)[64][SA],
                                              float acc[2][4][4],
                                              int m0, int o0, int tid)
{
    int lane = tid & 31, w = tid >> 5;
    int wm = w & 3, wn = w >> 2;
    int gID = lane >> 2, tig = lane & 3;
    int lmA = tid >> 1, lkA = (tid & 1) * 8;   // A: 2 thr/row, 8 words each
    int lmB = tid >> 2, lkB = (tid & 3) * 4;   // B: 4 thr/row, 4 words each

    for (int kc = 0; kc < 256; kc += 16) {
        float4 v0 = *(const float4*)&Xp[(m0 + lmA) * 256 + kc + lkA];
        float4 v1 = *(const float4*)&Xp[(m0 + lmA) * 256 + kc + lkA + 4];
        float4 u0 = *(const float4*)&W [(o0 + lmB) * 256 + kc + lkB];
        __syncthreads();
        {
            uint4 h4, l4;
            f2tf2(v0.x, h4.x, l4.x); f2tf2(v0.y, h4.y, l4.y);
            f2tf2(v0.z, h4.z, l4.z); f2tf2(v0.w, h4.w, l4.w);
            *(uint4*)&sAb[0][lmA][lkA]     = h4;
            *(uint4*)&sAb[1][lmA][lkA]     = l4;
            f2tf2(v1.x, h4.x, l4.x); f2tf2(v1.y, h4.y, l4.y);
            f2tf2(v1.z, h4.z, l4.z); f2tf2(v1.w, h4.w, l4.w);
            *(uint4*)&sAb[0][lmA][lkA + 4] = h4;
            *(uint4*)&sAb[1][lmA][lkA + 4] = l4;
            f2tf2(u0.x, h4.x, l4.x); f2tf2(u0.y, h4.y, l4.y);
            f2tf2(u0.z, h4.z, l4.z); f2tf2(u0.w, h4.w, l4.w);
            *(uint4*)&sBb[0][lmB][lkB]     = h4;
            *(uint4*)&sBb[1][lmB][lkB]     = l4;
        }
        __syncthreads();
        #pragma unroll
        for (int ks = 0; ks < 2; ks++) {
            int k8 = ks * 8;
            unsigned int ah[2][4], al[2][4];
            #pragma unroll
            for (int f = 0; f < 2; f++) {
                int r = wm * 32 + f * 16 + gID;
                ah[f][0] = sAb[0][r    ][k8 + tig];
                ah[f][1] = sAb[0][r + 8][k8 + tig];
                ah[f][2] = sAb[0][r    ][k8 + tig + 4];
                ah[f][3] = sAb[0][r + 8][k8 + tig + 4];
                al[f][0] = sAb[1][r    ][k8 + tig];
                al[f][1] = sAb[1][r + 8][k8 + tig];
                al[f][2] = sAb[1][r    ][k8 + tig + 4];
                al[f][3] = sAb[1][r + 8][k8 + tig + 4];
            }
            #pragma unroll
            for (int g = 0; g < 4; g++) {
                int c = wn * 32 + g * 8 + gID;
                unsigned int bh[2] = { sBb[0][c][k8 + tig], sBb[0][c][k8 + tig + 4] };
                unsigned int bl[2] = { sBb[1][c][k8 + tig], sBb[1][c][k8 + tig + 4] };
                #pragma unroll
                for (int f = 0; f < 2; f++) {
                    MMA_TF32(acc[f][g], ah[f], bh);
                    MMA_TF32(acc[f][g], ah[f], bl);
                    MMA_TF32(acc[f][g], al[f], bh);
                }
            }
        }
    }
}

// ---------------- fused Q/K/V projection GEMM (blockIdx.z selects q/k/v) ----------------
__global__ __launch_bounds__(256) void qkv_gemm(QKVPtrs P)
{
    __shared__ unsigned int sAb[2][128][SA];
    __shared__ unsigned int sBb[2][64][SA];

    int which = blockIdx.z;
    int m0 = blockIdx.x * 128;
    int o0 = blockIdx.y * 64;
    int tid = threadIdx.x;
    int lane = tid & 31, w = tid >> 5;
    int wm = w & 3, wn = w >> 2;
    int gID = lane >> 2, tig = lane & 3;

    float acc[2][4][4];
    #pragma unroll
    for (int f = 0; f < 2; f++)
        #pragma unroll
        for (int g = 0; g < 4; g++)
            #pragma unroll
            for (int i = 0; i < 4; i++) acc[f][g][i] = 0.f;

    gemm_core_mma(P.X[which], P.W[which], sAb, sBb, acc, m0, o0, tid);

    float* dst  = (which == 0) ? g_qh : ((which == 1) ? g_kh : g_vh);
    float* dstT = (which == 0) ? g_qhT : g_khT;   // used only when which < 2
    #pragma unroll
    for (int g = 0; g < 4; g++) {
        int oo = o0 + wn * 32 + g * 8 + 2 * tig;
        float2 bb = *(const float2*)&P.Bv[which][oo];
        int h = oo >> 5, d = oo & (ND - 1);
        #pragma unroll
        for (int f = 0; f < 2; f++) {
            #pragma unroll
            for (int rr = 0; rr < 2; rr++) {
                int m = m0 + wm * 32 + f * 16 + rr * 8 + gID;
                float y0 = acc[f][g][rr * 2 + 0] + bb.x;
                float y1 = acc[f][g][rr * 2 + 1] + bb.y;
                int b = m >> 9, n = m & (NN - 1);
                *(float2*)&dst[(((b * NH + h) * NN) + n) * ND + d] = make_float2(y0, y1);
                if (which < 2) {
                    int base = ((b * NH + h) * ND + d) * NN + n;
                    dstT[base]      = y0;
                    dstT[base + NN] = y1;
                }
            }
        }
    }
}

// ---------------- output projection GEMM: out = g_ao @ Wo^T + bo ----------------
__global__ __launch_bounds__(256) void out_gemm(const float* __restrict__ W,
                                                const float* __restrict__ bias,
                                                float* __restrict__ out)
{
    __shared__ unsigned int sAb[2][128][SA];
    __shared__ unsigned int sBb[2][64][SA];

    int m0 = blockIdx.x * 128;
    int o0 = blockIdx.y * 64;
    int tid = threadIdx.x;
    int lane = tid & 31, w = tid >> 5;
    int wm = w & 3, wn = w >> 2;
    int gID = lane >> 2, tig = lane & 3;

    float acc[2][4][4];
    #pragma unroll
    for (int f = 0; f < 2; f++)
        #pragma unroll
        for (int g = 0; g < 4; g++)
            #pragma unroll
            for (int i = 0; i < 4; i++) acc[f][g][i] = 0.f;

    gemm_core_mma(g_ao, W, sAb, sBb, acc, m0, o0, tid);

    #pragma unroll
    for (int g = 0; g < 4; g++) {
        int oo = o0 + wn * 32 + g * 8 + 2 * tig;
        float2 bb = *(const float2*)&bias[oo];
        #pragma unroll
        for (int f = 0; f < 2; f++) {
            #pragma unroll
            for (int rr = 0; rr < 2; rr++) {
                int m = m0 + wm * 32 + f * 16 + rr * 8 + gID;
                float y0 = acc[f][g][rr * 2 + 0] + bb.x;
                float y1 = acc[f][g][rr * 2 + 1] + bb.y;
                *(float2*)&out[m * NHID + oo] = make_float2(y0, y1);
            }
        }
    }
}

// ---------------- combined edge-type score table: g_qke[b][h][n][e] ----------------
__global__ __launch_bounds__(256) void edge_kernel(const float* __restrict__ qemb,
                                                   const float* __restrict__ kemb)
{
    int bh = blockIdx.x;
    int h = bh & (NH - 1);
    __shared__ float sq[NE * ND], sk[NE * ND];
    int tid = threadIdx.x;
    for (int t = tid; t < NE * ND; t += 256) {
        int e = t >> 5, d = t & 31;
        sq[t] = qemb[e * (NH * ND) + h * ND + d];
        sk[t] = kemb[e * (NH * ND) + h * ND + d];
    }
    __syncthreads();

    int n = blockIdx.y * 256 + tid;
    const float4* q4 = (const float4*)&g_qh[((size_t)bh * NN + n) * ND];
    const float4* k4 = (const float4*)&g_kh[((size_t)bh * NN + n) * ND];

    float acc[NE];
    #pragma unroll
    for (int e = 0; e < NE; e++) acc[e] = 0.f;

    #pragma unroll
    for (int g = 0; g < 8; g++) {
        float4 qv = q4[g];
        float4 kv = k4[g];
        #pragma unroll
        for (int e = 0; e < NE; e++) {
            const float4 s1 = *(const float4*)&sq[e * ND + g * 4];
            const float4 s2 = *(const float4*)&sk[e * ND + g * 4];
            float a = acc[e];
            a = fmaf(qv.x, s1.x, a);
            a = fmaf(qv.y, s1.y, a);
            a = fmaf(qv.z, s1.z, a);
            a = fmaf(qv.w, s1.w, a);
            a = fmaf(kv.x, s2.x, a);
            a = fmaf(kv.y, s2.y, a);
            a = fmaf(kv.z, s2.z, a);
            a = fmaf(kv.w, s2.w, a);
            acc[e] = a;
        }
    }

    float4* out = (float4*)&g_qke[((size_t)bh * NN + n) * NE];
    out[0] = make_float4(acc[0],  acc[1],  acc[2],  acc[3]);
    out[1] = make_float4(acc[4],  acc[5],  acc[6],  acc[7]);
    out[2] = make_float4(acc[8],  acc[9],  acc[10], acc[11]);
    out[3] = make_float4(acc[12], acc[13], acc[14], acc[15]);
}

// ---------------- fused attention: one CTA = (b, h, 32-row i-tile) ----------------
// (reverted to the best R12 form: PV reads V straight from gmem/L2)
__global__ __launch_bounds__(256, 2) void attn_kernel(const int* __restrict__ edge_attr,
                                                      const int* __restrict__ mask,
                                                      const int* __restrict__ fmask)
{
    extern __shared__ float sm[];
    float* buf0 = sm;                 // 16512 floats: K^T [d][512], then P [32] stride 516
    float* sQT  = sm + 16512;         // [d][32]
    float* sQE  = sQT + 1024;         // [32][16]
    float* sMb  = sQE + 512;          // additive key mask (0 / -inf)

    int it = blockIdx.x, h = blockIdx.y, b = blockIdx.z;
    int bh = b * NH + h;
    int gi0 = it * 32;
    int tid = threadIdx.x;

    {   // K^T tile: contiguous 64KB copy
        const float4* srcK = (const float4*)(g_khT + (size_t)bh * ND * NN);
        float4* dstK = (float4*)buf0;
        for (int t = tid; t < 4096; t += 256) dstK[t] = srcK[t];
    }
    {   // Q^T 32x32 sub-tile
        const float* qT = g_qhT + (size_t)bh * ND * NN;
        for (int t = tid; t < 1024; t += 256)
            sQT[t] = qT[(t >> 5) * NN + gi0 + (t & 31)];
    }
    {   // combined edge table rows for this i-tile
        const float* src = g_qke + ((size_t)bh * NN + gi0) * NE;
        for (int t = tid; t < 512; t += 256) sQE[t] = src[t];
    }
    for (int t = tid; t < NN; t += 256)
        sMb[t] = mask[b * NN + t] ? 0.f : -INFINITY;
    __syncthreads();

    int tr = tid >> 5, tc = tid & 31;   // tr: i-group (warp id), tc: lane
    int i0 = tr * 4;
    const ulonglong2* KT2 = (const ulonglong2*)buf0;   // [d][128] col-pairs
    const float4*     QT4 = (const float4*)sQT;        // [d][8]
    bool focal = (h >= GHEADS);

    // ---- S = scale*(Q K^T + bias) + mask, kept in registers ----
    float S[4][16];   // [row a][pass*4 + c]
    #pragma unroll
    for (int pass = 0; pass < 4; pass++) {
        int jg = pass * 32 + tc;
        unsigned long long accP[4][2];
        #pragma unroll
        for (int a = 0; a < 4; a++) { accP[a][0] = 0ull; accP[a][1] = 0ull; }
        #pragma unroll 8
        for (int d = 0; d < 32; d++) {
            ulonglong2 k2 = KT2[d * 128 + jg];         // (c0,c1),(c2,c3)
            float4 q4 = QT4[d * 8 + tr];
            unsigned long long qs0, qs1, qs2, qs3;
            PACKF2(qs0, q4.x); PACKF2(qs1, q4.y); PACKF2(qs2, q4.z); PACKF2(qs3, q4.w);
            FMA2(accP[0][0], qs0, k2.x); FMA2(accP[0][1], qs0, k2.y);
            FMA2(accP[1][0], qs1, k2.x); FMA2(accP[1][1], qs1, k2.y);
            FMA2(accP[2][0], qs2, k2.x); FMA2(accP[2][1], qs2, k2.y);
            FMA2(accP[3][0], qs3, k2.x); FMA2(accP[3][1], qs3, k2.y);
        }
        int j0 = jg * 4;
        #pragma unroll
        for (int a = 0; a < 4; a++) {
            float ac0, ac1, ac2, ac3;
            UNPACKF2(ac0, ac1, accP[a][0]);
            UNPACKF2(ac2, ac3, accP[a][1]);
            int gi = gi0 + i0 + a;
            int4 e4 = *(const int4*)&edge_attr[((size_t)b * NN + gi) * NN + j0];
            float mb0, mb1, mb2, mb3;
            if (focal) {
                int4 f4 = *(const int4*)&fmask[((size_t)b * NN + gi) * NN + j0];
                mb0 = f4.x ? 0.f : -INFINITY;
                mb1 = f4.y ? 0.f : -INFINITY;
                mb2 = f4.z ? 0.f : -INFINITY;
                mb3 = f4.w ? 0.f : -INFINITY;
            } else {
                mb0 = sMb[j0]; mb1 = sMb[j0+1]; mb2 = sMb[j0+2]; mb3 = sMb[j0+3];
            }
            const float* qe = &sQE[(i0 + a) * NE];
            S[a][pass*4+0] = (ac0 + qe[e4.x]) * ATT_SCALE + mb0;
            S[a][pass*4+1] = (ac1 + qe[e4.y]) * ATT_SCALE + mb1;
            S[a][pass*4+2] = (ac2 + qe[e4.z]) * ATT_SCALE + mb2;
            S[a][pass*4+3] = (ac3 + qe[e4.w]) * ATT_SCALE + mb3;
        }
    }

    // ---- softmax fully in registers: row a is spread over this warp's 32 lanes ----
    #pragma unroll
    for (int a = 0; a < 4; a++) {
        float m = S[a][0];
        #pragma unroll
        for (int c = 1; c < 16; c++) m = fmaxf(m, S[a][c]);
        m = fmaxf(m, __shfl_xor_sync(0xffffffffu, m, 16));
        m = fmaxf(m, __shfl_xor_sync(0xffffffffu, m, 8));
        m = fmaxf(m, __shfl_xor_sync(0xffffffffu, m, 4));
        m = fmaxf(m, __shfl_xor_sync(0xffffffffu, m, 2));
        m = fmaxf(m, __shfl_xor_sync(0xffffffffu, m, 1));
        float l = 0.f;
        #pragma unroll
        for (int c = 0; c < 16; c++) {
            float p = __expf(S[a][c] - m);
            S[a][c] = p;
            l += p;
        }
        l += __shfl_xor_sync(0xffffffffu, l, 16);
        l += __shfl_xor_sync(0xffffffffu, l, 8);
        l += __shfl_xor_sync(0xffffffffu, l, 4);
        l += __shfl_xor_sync(0xffffffffu, l, 2);
        l += __shfl_xor_sync(0xffffffffu, l, 1);
        float inv = 1.f / l;
        #pragma unroll
        for (int c = 0; c < 16; c++) S[a][c] *= inv;
    }

    __syncthreads();   // all warps done reading K^T -> safe to overwrite with P

    // ---- write normalized P over the dead K^T buffer, [i][j] stride PSTRIDE ----
    #pragma unroll
    for (int pass = 0; pass < 4; pass++) {
        int j0 = (pass * 32 + tc) * 4;
        #pragma unroll
        for (int a = 0; a < 4; a++)
            *(float4*)&buf0[(i0 + a) * PSTRIDE + j0] =
                make_float4(S[a][pass*4+0], S[a][pass*4+1], S[a][pass*4+2], S[a][pass*4+3]);
    }
    __syncwarp();   // PV reads only this warp's own P rows -> warp-local ordering suffices

    // ---- O = P V (f32x2): thread = 4 i-rows x 4 d-cols, 4-way j split; V from gmem ----
    {
        int dg = tc & 7, js = tc >> 3;
        const ulonglong2* V2 = (const ulonglong2*)(g_vh + (size_t)bh * NN * ND);  // [j][8]
        unsigned long long oP[4][2];
        #pragma unroll
        for (int a = 0; a < 4; a++) { oP[a][0] = 0ull; oP[a][1] = 0ull; }
        #pragma unroll 8
        for (int j = js; j < NN; j += 4) {
            ulonglong2 vv = V2[j * 8 + dg];            // (d0,d1),(d2,d3)
            float p0 = buf0[(i0+0) * PSTRIDE + j];
            float p1 = buf0[(i0+1) * PSTRIDE + j];
            float p2 = buf0[(i0+2) * PSTRIDE + j];
            float p3 = buf0[(i0+3) * PSTRIDE + j];
            unsigned long long ps0, ps1, ps2, ps3;
            PACKF2(ps0, p0); PACKF2(ps1, p1); PACKF2(ps2, p2); PACKF2(ps3, p3);
            FMA2(oP[0][0], ps0, vv.x); FMA2(oP[0][1], ps0, vv.y);
            FMA2(oP[1][0], ps1, vv.x); FMA2(oP[1][1], ps1, vv.y);
            FMA2(oP[2][0], ps2, vv.x); FMA2(oP[2][1], ps2, vv.y);
            FMA2(oP[3][0], ps3, vv.x); FMA2(oP[3][1], ps3, vv.y);
        }
        float4 o0, o1, o2, o3;
        UNPACKF2(o0.x, o0.y, oP[0][0]); UNPACKF2(o0.z, o0.w, oP[0][1]);
        UNPACKF2(o1.x, o1.y, oP[1][0]); UNPACKF2(o1.z, o1.w, oP[1][1]);
        UNPACKF2(o2.x, o2.y, oP[2][0]); UNPACKF2(o2.z, o2.w, oP[2][1]);
        UNPACKF2(o3.x, o3.y, oP[3][0]); UNPACKF2(o3.z, o3.w, oP[3][1]);
        #define WRED(v) \
            v.x += __shfl_xor_sync(0xffffffffu, v.x, 8);  v.x += __shfl_xor_sync(0xffffffffu, v.x, 16); \
            v.y += __shfl_xor_sync(0xffffffffu, v.y, 8);  v.y += __shfl_xor_sync(0xffffffffu, v.y, 16); \
            v.z += __shfl_xor_sync(0xffffffffu, v.z, 8);  v.z += __shfl_xor_sync(0xffffffffu, v.z, 16); \
            v.w += __shfl_xor_sync(0xffffffffu, v.w, 8);  v.w += __shfl_xor_sync(0xffffffffu, v.w, 16);
        WRED(o0) WRED(o1) WRED(o2) WRED(o3)
        #undef WRED
        if (js == 0) {
            int col = h * ND + dg * 4;
            size_t rb = ((size_t)b * NN + gi0 + i0) * NHID;
            *(float4*)&g_ao[rb            + col] = o0;
            *(float4*)&g_ao[rb +     NHID + col] = o1;
            *(float4*)&g_ao[rb + 2 * NHID + col] = o2;
            *(float4*)&g_ao[rb + 3 * NHID + col] = o3;
        }
    }
}

// ---------------- launch ----------------
extern "C" void kernel_launch(void* const* d_in, const int* in_sizes, int n_in,
                              void* d_out, int out_size)
{
    const float* q    = (const float*)d_in[0];
    const float* k    = (const float*)d_in[1];
    const float* v    = (const float*)d_in[2];
    const float* qemb = (const float*)d_in[3];
    const float* kemb = (const float*)d_in[4];
    const int*   eatt = (const int*)d_in[5];
    const int*   mask  = (const int*)d_in[6];
    const int*   fmask = (const int*)d_in[7];
    const float* Wq = (const float*)d_in[8];
    const float* bq = (const float*)d_in[9];
    const float* Wk = (const float*)d_in[10];
    const float* bk = (const float*)d_in[11];
    const float* Wv = (const float*)d_in[12];
    const float* bv = (const float*)d_in[13];
    const float* Wo = (const float*)d_in[14];
    const float* bo = (const float*)d_in[15];
    float* out = (float*)d_out;

    QKVPtrs P;
    P.X[0] = q;  P.X[1] = k;  P.X[2] = v;
    P.W[0] = Wq; P.W[1] = Wk; P.W[2] = Wv;
    P.Bv[0] = bq; P.Bv[1] = bk; P.Bv[2] = bv;

    qkv_gemm<<<dim3(64, 4, 3), 256>>>(P);

    edge_kernel<<<dim3(NB * NH, 2), 256>>>(qemb, kemb);

    int smem_bytes = (16512 + 1024 + 512 + 512) * 4;  // 74,240 B -> 2 CTAs/SM
    cudaFuncSetAttribute(attn_kernel, cudaFuncAttributeMaxDynamicSharedMemorySize, smem_bytes);
    attn_kernel<<<dim3(NN / 32, NH, NB), 256, smem_bytes>>>(eatt, mask, fmask);

    out_gemm<<<dim3(64, 4), 256>>>(Wo, bo, out);
}